// round 15
// baseline (speedup 1.0000x reference)
#include <cuda_runtime.h>
#include <cuda_fp16.h>

#define B_    32
#define NS    128
#define SD    256
#define NF    4096
#define MH    1024
#define NMT   32

// ---------------- device scratch ----------------
__device__ float g_h[4][64];
__device__ __align__(16) __half g_Wq_h [SD*SD];
__device__ __align__(16) __half g_Wg_h [SD*2*SD];
__device__ __align__(16) __half g_Wf0_h[MH*2*SD];
__device__ __align__(16) __half g_Wf1_h[SD*MH];
__device__ __align__(16) __half g_snA_h[B_*NS*SD];
__device__ __align__(16) __half g_snF_h[B_*NS*SD];
__device__ __align__(16) __half g_q_h  [B_*NS*SD];
__device__ __align__(16) __half g_att_h[(size_t)B_*NS*NF];   // 32 MB fp16 probs
__device__ __align__(16) __half g_fattn_h[B_*NS*SD];
__device__ __align__(16) __half g_Hbuf_h[B_*NS*MH];
__device__ float g_srow[B_*NMT*NS];
__device__ float g_avp[(size_t)4*B_*NS*SD];
__device__ __align__(16) float g_fattn[B_*NS*SD];

// ---------------- helpers ----------------
#define CP_COMMIT asm volatile("cp.async.commit_group;\n" ::: "memory")
#define CP_WAIT0  asm volatile("cp.async.wait_group 0;\n" ::: "memory")
#define CP_WAIT1  asm volatile("cp.async.wait_group 1;\n" ::: "memory")
__device__ __forceinline__ void cpa16(unsigned d, const void* s) {
    asm volatile("cp.async.ca.shared.global [%0], [%1], 16;\n" :: "r"(d), "l"(s));
}
__device__ __forceinline__ void mma16(float c[4], const unsigned a[4], const unsigned b[2]) {
    asm volatile("mma.sync.aligned.m16n8k16.row.col.f32.f16.f16.f32 "
        "{%0,%1,%2,%3},{%4,%5,%6,%7},{%8,%9},{%0,%1,%2,%3};"
        : "+f"(c[0]), "+f"(c[1]), "+f"(c[2]), "+f"(c[3])
        : "r"(a[0]), "r"(a[1]), "r"(a[2]), "r"(a[3]), "r"(b[0]), "r"(b[1]));
}
__device__ __forceinline__ void ldsm4(unsigned r[4], unsigned addr) {
    asm volatile("ldmatrix.sync.aligned.m8n8.x4.shared.b16 {%0,%1,%2,%3}, [%4];"
        : "=r"(r[0]), "=r"(r[1]), "=r"(r[2]), "=r"(r[3]) : "r"(addr));
}
__device__ __forceinline__ void ldsm4t(unsigned r[4], unsigned addr) {
    asm volatile("ldmatrix.sync.aligned.m8n8.x4.trans.shared.b16 {%0,%1,%2,%3}, [%4];"
        : "=r"(r[0]), "=r"(r[1]), "=r"(r[2]), "=r"(r[3]) : "r"(addr));
}
__device__ __forceinline__ uint4 pack8(const float4& a, const float4& b) {
    __half2 h0 = __floats2half2_rn(a.x, a.y), h1 = __floats2half2_rn(a.z, a.w);
    __half2 h2 = __floats2half2_rn(b.x, b.y), h3 = __floats2half2_rn(b.z, b.w);
    uint4 u;
    u.x = *(unsigned*)&h0; u.y = *(unsigned*)&h1;
    u.z = *(unsigned*)&h2; u.w = *(unsigned*)&h3;
    return u;
}

// ---- cp.async of a BM x 32-half tile, smem row stride 80 B ----
template<int BM>
__device__ __forceinline__ void cpa_tile16(unsigned sb, const __half* a0, int lda0,
                                           const __half* a1, int lda1, int split,
                                           int k0, int tid)
{
    if (BM == 128) {
        int r = tid >> 1, s = tid & 1;
        #pragma unroll
        for (int j = 0; j < 2; j++) {
            int k = k0 + s*16 + j*8;
            const __half* src = (k < split) ? a0 + (size_t)r*lda0 + k
                                            : a1 + (size_t)r*lda1 + (k - split);
            cpa16(sb + (unsigned)(r*80 + s*32 + j*16), src);
        }
    } else {   // BM == 64
        int r = tid >> 2, s = tid & 3;
        int k = k0 + s*8;
        const __half* src = (k < split) ? a0 + (size_t)r*lda0 + k
                                        : a1 + (size_t)r*lda1 + (k - split);
        cpa16(sb + (unsigned)(r*80 + s*16), src);
    }
}

// ---- mma.sync inner compute: BK=32 chunk, A/B in [rows][32k] 80B-stride ----
template<int MT, int NT16>
__device__ __forceinline__ void comp16(unsigned Ab, unsigned Bb,
                                       float acc[][NT16*2][4], int wr, int wc, int lane)
{
    int quad = lane >> 3, l7 = lane & 7;
    #pragma unroll
    for (int s = 0; s < 2; s++) {
        unsigned a[MT][4];
        #pragma unroll
        for (int mt = 0; mt < MT; mt++)
            ldsm4(a[mt], Ab + (unsigned)((wr + mt*16 + (quad&1)*8 + l7)*80 + s*32 + (quad>>1)*16));
        #pragma unroll
        for (int nt16 = 0; nt16 < NT16; nt16++) {
            unsigned bm4[4];
            ldsm4(bm4, Bb + (unsigned)((wc + nt16*16 + (quad>>1)*8 + l7)*80 + s*32 + (quad&1)*16));
            #pragma unroll
            for (int oct = 0; oct < 2; oct++)
                #pragma unroll
                for (int mt = 0; mt < MT; mt++)
                    mma16(acc[mt][nt16*2+oct], a[mt], &bm4[oct*2]);
        }
    }
}
// ---- AV inner compute (512-thr layout): warp owns 32 rows x 64 cols ----
__device__ __forceinline__ void comp16_av2(unsigned Ab, unsigned Bb,
                                           float av[2][8][4], int wr, int wc2, int lane)
{
    int quad = lane >> 3, l7 = lane & 7;
    #pragma unroll
    for (int s = 0; s < 2; s++) {
        unsigned a[2][4];
        #pragma unroll
        for (int m2 = 0; m2 < 2; m2++)
            ldsm4(a[m2], Ab + (unsigned)((wr + m2*16 + (quad&1)*8 + l7)*80 + s*32 + (quad>>1)*16));
        #pragma unroll
        for (int nt16 = 0; nt16 < 4; nt16++) {
            unsigned bm4[4];
            ldsm4t(bm4, Bb + (unsigned)((s*16 + (quad&1)*8 + l7)*528 + (wc2 + nt16*16 + (quad>>1)*8)*2));
            #pragma unroll
            for (int oct = 0; oct < 2; oct++)
                #pragma unroll
                for (int m2 = 0; m2 < 2; m2++)
                    mma16(av[m2][nt16*2+oct], a[m2], &bm4[oct*2]);
        }
    }
}

// ---- 3-stage cp.async pipelined fp16 GEMM; NB = B tile rows (64 or 128) ----
template<int MT, int NB>
__device__ __forceinline__ void h_gemm_async3(unsigned sbase,
    const __half* a0, int lda0, const __half* a1, int lda1, int split,
    const __half* b, int ldb, int nchunks,
    float acc[][NB/16][4], int wr, int wc, int lane, int tid)
{
    const unsigned ABUF = MT*64*80, BBUF = NB*80;
    unsigned st[3];
    #pragma unroll
    for (int s = 0; s < 3; s++) st[s] = sbase + (unsigned)s*(ABUF + BBUF);
    #pragma unroll
    for (int s = 0; s < 2; s++) {
        cpa_tile16<MT*64>(st[s], a0, lda0, a1, lda1, split, s*32, tid);
        cpa_tile16<NB>(st[s] + ABUF, b, ldb, b, ldb, 1<<30, s*32, tid);
        CP_COMMIT;
    }
    for (int c = 0; c < nchunks; c++) {
        CP_WAIT1;
        __syncthreads();
        int cn = c + 2;
        if (cn < nchunks) {
            unsigned ss = st[cn % 3];
            cpa_tile16<MT*64>(ss, a0, lda0, a1, lda1, split, cn*32, tid);
            cpa_tile16<NB>(ss + ABUF, b, ldb, b, ldb, 1<<30, cn*32, tid);
        }
        CP_COMMIT;
        unsigned sc = st[c % 3];
        comp16<MT, NB/32>(sc, sc + ABUF, acc, wr, wc, lane);
    }
    CP_WAIT0;
    __syncthreads();
}

// ---- staged fp32->fp16 loaders ----
__device__ __forceinline__ void ldgK(float4 p[4], const float* Kb, int k0, int tid) {
    int n = tid >> 1, c0 = (tid & 1) * 16;
    const float* s = Kb + (size_t)n*256 + k0 + c0;
    #pragma unroll
    for (int j = 0; j < 4; j++) p[j] = ((const float4*)s)[j];
}
__device__ __forceinline__ void stsK(unsigned char* buf, const float4 p[4], int tid) {
    int n = tid >> 1, c0 = tid & 1;
    *(uint4*)(buf + n*80 + c0*32)      = pack8(p[0], p[1]);
    *(uint4*)(buf + n*80 + c0*32 + 16) = pack8(p[2], p[3]);
}
__device__ __forceinline__ void ldgV512(float4 p[4], const float* Vb, int m0, int tid) {
    int k = tid >> 4, d0 = (tid & 15) * 16;
    const float* s = Vb + (size_t)(m0 + k)*256 + d0;
    #pragma unroll
    for (int j = 0; j < 4; j++) p[j] = ((const float4*)s)[j];
}
__device__ __forceinline__ void stsV512(unsigned char* buf, const float4 p[4], int tid) {
    int k = tid >> 4, d0 = (tid & 15) * 16;
    *(uint4*)(buf + k*528 + d0*2)      = pack8(p[0], p[1]);
    *(uint4*)(buf + k*528 + d0*2 + 16) = pack8(p[2], p[3]);
}

// ---- W-materialize row compute (8 warps x 8 rows per 256-thr CTA) ----
__device__ __forceinline__ void wmat_compute(const float* __restrict__ wp,
                                             const float* __restrict__ bp,
                                             const float* __restrict__ hv,
                                             __half* W, int r, int sub)
{
    float p = 0.f;
    #pragma unroll
    for (int j = 0; j < 4; j++) {
        float4 w  = *(const float4*)&wp[(size_t)r*64 + sub*16 + 4*j];
        float4 hh = *(const float4*)&hv[sub*16 + 4*j];
        p += w.x*hh.x + w.y*hh.y + w.z*hh.z + w.w*hh.w;
    }
    p += __shfl_down_sync(0xffffffffu, p, 2);
    p += __shfl_down_sync(0xffffffffu, p, 1);
    if (sub == 0) W[r] = __float2half_rn(p + bp[r]);
}

// ---------------- 1) time MLP heads ----------------
__global__ void tdw_kernel(const float* t,
    const float* qw0,const float* qb0,const float* qw1,const float* qb1,
    const float* gw0,const float* gb0,const float* gw1,const float* gb1,
    const float* f0w0,const float* f0b0,const float* f0w1,const float* f0b1,
    const float* f1w0,const float* f1b0,const float* f1w1,const float* f1b1)
{
    __shared__ float emb[257];
    __shared__ float h0[64];
    const float* w0s[4] = {qw0,gw0,f0w0,f1w0};
    const float* b0s[4] = {qb0,gb0,f0b0,f1b0};
    const float* w1s[4] = {qw1,gw1,f0w1,f1w1};
    const float* b1s[4] = {qb1,gb1,f0b1,f1b1};
    int head = blockIdx.x, tid = threadIdx.x;
    float tv = t[0];
    const float C = -9.210340371976184f / 128.0f;
    for (int j = tid; j < 257; j += blockDim.x) {
        float e;
        if (j == 0)        e = tv;
        else if (j <= 128) e = sinf(C * (float)(j-1)   * tv);
        else               e = cosf(C * (float)(j-129) * tv);
        emb[j] = e;
    }
    __syncthreads();
    int warp = tid >> 5, lane = tid & 31;
    const float* w0 = w0s[head];
    for (int r = warp; r < 64; r += 4) {
        float s = 0.f;
        for (int j = lane; j < 257; j += 32) s += w0[r*257 + j] * emb[j];
        #pragma unroll
        for (int o = 16; o; o >>= 1) s += __shfl_xor_sync(0xffffffffu, s, o);
        if (lane == 0) { s += b0s[head][r]; h0[r] = s / (1.f + expf(-s)); }
    }
    __syncthreads();
    if (tid < 64) {
        const float* w1 = w1s[head];
        float s = 0.f;
        #pragma unroll 8
        for (int j = 0; j < 64; j++) s += w1[tid*64 + j] * h0[j];
        s += b1s[head][tid];
        g_h[head][tid] = s / (1.f + expf(-s));
    }
}

// ---------------- 2a) materialize Wq (stream 0, needed by gemm_q) ----------------
__global__ void wmat_q_kernel(const float* __restrict__ wp, const float* __restrict__ bp)
{
    int wid = threadIdx.x >> 5, lane = threadIdx.x & 31;
    int rl = lane >> 2, sub = lane & 3;
    int r = (blockIdx.x * 8 + wid) * 8 + rl;     // < 65536
    wmat_compute(wp, bp, g_h[0], g_Wq_h, r, sub);
}

// ---------------- 2b) materialize Wg/Wf0/Wf1 (side stream) ----------------
__global__ void wmat_rest_kernel(const float* __restrict__ wp_g,  const float* __restrict__ bp_g,
                                 const float* __restrict__ wp_f0, const float* __restrict__ bp_f0,
                                 const float* __restrict__ wp_f1, const float* __restrict__ bp_f1)
{
    int wid = threadIdx.x >> 5, lane = threadIdx.x & 31;
    int rl = lane >> 2, sub = lane & 3;
    int r8 = 65536 + ((blockIdx.x * 8 + wid) * 8 + rl);
    const float* wp; const float* bp; __half* W; int r; int which;
    if (r8 < 196608)      { wp = wp_g;  bp = bp_g;  W = g_Wg_h;  r = r8 - 65536;  which = 1; }
    else if (r8 < 720896) { wp = wp_f0; bp = bp_f0; W = g_Wf0_h; r = r8 - 196608; which = 2; }
    else                  { wp = wp_f1; bp = bp_f1; W = g_Wf1_h; r = r8 - 720896; which = 3; }
    wmat_compute(wp, bp, g_h[which], W, r, sub);
}

// ---------------- 3) dual LayerNorm (fp16 out; side stream, no deps) ----------------
__global__ void ln_kernel(const float* __restrict__ slots,
                          const float* __restrict__ aw, const float* __restrict__ ab,
                          const float* __restrict__ fw, const float* __restrict__ fb)
{
    int warp = threadIdx.x >> 5, lane = threadIdx.x & 31;
    int row  = blockIdx.x * 8 + warp;
    const float* x = slots + (size_t)row * 256;
    float v[8];
    *(float4*)&v[0] = *(const float4*)&x[lane*4];
    *(float4*)&v[4] = *(const float4*)&x[128 + lane*4];
    float s = 0.f;
    #pragma unroll
    for (int i = 0; i < 8; i++) s += v[i];
    #pragma unroll
    for (int o = 16; o; o >>= 1) s += __shfl_xor_sync(0xffffffffu, s, o);
    float mu = s * (1.f/256.f);
    float q = 0.f;
    #pragma unroll
    for (int i = 0; i < 8; i++) { float d = v[i]-mu; q += d*d; }
    #pragma unroll
    for (int o = 16; o; o >>= 1) q += __shfl_xor_sync(0xffffffffu, q, o);
    float rstd = rsqrtf(q * (1.f/256.f) + 1e-5f);
    #pragma unroll
    for (int h = 0; h < 2; h++) {
        int base = h ? 128 + lane*4 : lane*4;
        float4 awv = *(const float4*)&aw[base], abv = *(const float4*)&ab[base];
        float4 fwv = *(const float4*)&fw[base], fbv = *(const float4*)&fb[base];
        const float* vv = &v[h*4];
        float A0=(vv[0]-mu)*rstd*awv.x+abv.x, A1=(vv[1]-mu)*rstd*awv.y+abv.y;
        float A2=(vv[2]-mu)*rstd*awv.z+abv.z, A3=(vv[3]-mu)*rstd*awv.w+abv.w;
        float F0=(vv[0]-mu)*rstd*fwv.x+fbv.x, F1=(vv[1]-mu)*rstd*fwv.y+fbv.y;
        float F2=(vv[2]-mu)*rstd*fwv.z+fbv.z, F3=(vv[3]-mu)*rstd*fwv.w+fbv.w;
        __half2 a01 = __floats2half2_rn(A0, A1), a23 = __floats2half2_rn(A2, A3);
        __half2 f01 = __floats2half2_rn(F0, F1), f23 = __floats2half2_rn(F2, F3);
        *(uint2*)&g_snA_h[(size_t)row*256 + base] = make_uint2(*(unsigned*)&a01, *(unsigned*)&a23);
        *(uint2*)&g_snF_h[(size_t)row*256 + base] = make_uint2(*(unsigned*)&f01, *(unsigned*)&f23);
    }
}

// ---------------- 4) q = snA @ Wq^T (BM=64, BN=64, grid 256) ----------------
__global__ __launch_bounds__(256) void gemm_q_h()
{
    extern __shared__ unsigned char smp[];
    unsigned sbase = (unsigned)__cvta_generic_to_shared(smp);
    int tid = threadIdx.x, lane = tid & 31;
    int g = lane >> 2, t = lane & 3;
    int wid = tid >> 5, wr = (wid >> 1) * 16, wc = (wid & 1) * 32;
    int bm = blockIdx.x * 64, bn = blockIdx.y * 64;
    float acc[1][4][4] = {};
    h_gemm_async3<1, 64>(sbase, g_snA_h + (size_t)bm*256, 256, g_snA_h, 256, 1<<30,
                         g_Wq_h + (size_t)bn*256, 256, 8, acc, wr, wc, lane, tid);
    #pragma unroll
    for (int nt = 0; nt < 4; nt++) {
        int r = bm + wr + g, c = bn + wc + nt*8 + 2*t;
        __half2 h0 = __floats2half2_rn(acc[0][nt][0], acc[0][nt][1]);
        __half2 h1 = __floats2half2_rn(acc[0][nt][2], acc[0][nt][3]);
        *(__half2*)&g_q_h[(size_t)r*256 + c]     = h0;
        *(__half2*)&g_q_h[(size_t)(r+8)*256 + c] = h1;
    }
}

// ---------------- 5) QK^T + softmax -> fp16 probs (3 CTAs/SM) ----------------
#define QK_RED  67584u
#define QK_SMEM 68608

__global__ __launch_bounds__(256, 3) void attn_qk_kernel(const float* __restrict__ Kin)
{
    extern __shared__ unsigned char smp[];
    unsigned sbase = (unsigned)__cvta_generic_to_shared(smp);
    float* L   = (float*)smp;
    float* RED = (float*)(smp + QK_RED);
    unsigned qoff[2] = {sbase, sbase + 10240u};
    unsigned koff[2] = {sbase + 20480u, sbase + 30720u};
    int bid = blockIdx.x;
    int b = bid >> 5, mt_ = bid & 31;
    int tid = threadIdx.x, lane = tid & 31;
    int g = lane >> 2, t = lane & 3;
    int wid = tid >> 5, wr = (wid >> 1) * 32, wc = (wid & 1) * 64;
    const __half* Q = g_q_h + (size_t)b*128*256;
    const float* Kb = Kin + ((size_t)b*NF + mt_*128)*256;
    float qk[2][8][4] = {};
    cpa_tile16<128>(qoff[0], Q, 256, Q, 256, 1<<30, 0, tid);
    CP_COMMIT;
    float4 pk[4];
    ldgK(pk, Kb, 0, tid);
    for (int c = 0; c < 8; c++) {
        stsK(smp + 20480 + (c&1)*10240, pk, tid);
        CP_WAIT0; __syncthreads();
        if (c < 7) {
            cpa_tile16<128>(qoff[(c+1)&1], Q, 256, Q, 256, 1<<30, (c+1)*32, tid);
            CP_COMMIT;
            ldgK(pk, Kb, (c+1)*32, tid);
        }
        comp16<2, 4>(qoff[c&1], koff[c&1], qk, wr, wc, lane);
    }
    __syncthreads();
    const float scale = 0.0625f;
    #pragma unroll
    for (int m2 = 0; m2 < 2; m2++)
        #pragma unroll
        for (int nt = 0; nt < 8; nt++) {
            int r = wr + m2*16 + g, c = wc + nt*8 + 2*t;
            L[r*132 + c]       = qk[m2][nt][0]*scale;
            L[r*132 + c+1]     = qk[m2][nt][1]*scale;
            L[(r+8)*132 + c]   = qk[m2][nt][2]*scale;
            L[(r+8)*132 + c+1] = qk[m2][nt][3]*scale;
        }
    __syncthreads();
    int half = tid >> 7, m = tid & 127, r0 = half * 64;
    float mx = -1e30f;
    #pragma unroll 8
    for (int r = 0; r < 64; r++) mx = fmaxf(mx, L[(r0+r)*132 + m]);
    RED[half*128 + m] = mx;
    __syncthreads();
    mx = fmaxf(RED[m], RED[128 + m]);
    float s = 0.f;
    #pragma unroll 8
    for (int r = 0; r < 64; r++) {
        float e = __expf(L[(r0+r)*132 + m] - mx);
        L[(r0+r)*132 + m] = e;
        s += e;
    }
    __syncthreads();
    RED[half*128 + m] = s;
    __syncthreads();
    float inv = 1.f / (RED[m] + RED[128 + m]);
    #pragma unroll 8
    for (int r = 0; r < 64; r++) L[(r0+r)*132 + m] *= inv;
    __syncthreads();
    {
        int n = m;
        float rs = 0.f;
        #pragma unroll 8
        for (int j = 0; j < 64; j++) rs += L[n*132 + half*64 + j];
        RED[half*128 + n] = rs;
    }
    __syncthreads();
    if (tid < 128)
        g_srow[((size_t)b*NMT + mt_)*128 + tid] = RED[tid] + RED[128 + tid];
    int n = tid >> 1, mh = (tid & 1) * 64;
    __half* dst = g_att_h + ((size_t)b*128 + n)*NF + mt_*128 + mh;
    #pragma unroll
    for (int j = 0; j < 8; j++) {
        float4 v0 = *(float4*)&L[n*132 + mh + 8*j];
        float4 v1 = *(float4*)&L[n*132 + mh + 8*j + 4];
        *(uint4*)(dst + 8*j) = pack8(v0, v1);
    }
}

// ---------------- 6) att @ V (split-K=4, 512 threads) ----------------
// smem: A probs dbl [0,20480), V dbl [20480, 20480+2*16896) = 54272 B
__global__ __launch_bounds__(512) void attn_av_kernel(const float* __restrict__ Vin)
{
    extern __shared__ unsigned char smp[];
    unsigned sbase = (unsigned)__cvta_generic_to_shared(smp);
    unsigned aoff[2] = {sbase, sbase + 10240u};
    int b = blockIdx.x, ks = blockIdx.y;
    int tid = threadIdx.x, lane = tid & 31;
    int g = lane >> 2, t = lane & 3;
    int wid = tid >> 5;
    int wr  = (wid >> 2) * 32;
    int wc2 = (wid & 3) * 64;
    const __half* Ap = g_att_h + (size_t)b*128*NF + ks*1024;
    const float* Vb = Vin + ((size_t)b*NF + ks*1024)*256;
    float av[2][8][4];
    #pragma unroll
    for (int i = 0; i < 2; i++)
        #pragma unroll
        for (int j = 0; j < 8; j++)
            #pragma unroll
            for (int k = 0; k < 4; k++) av[i][j][k] = 0.f;
    if (tid < 256) cpa_tile16<128>(aoff[0], Ap, NF, Ap, NF, 1<<30, 0, tid);
    CP_COMMIT;
    float4 pv[4];
    ldgV512(pv, Vb, 0, tid);
    for (int c = 0; c < 32; c++) {
        stsV512(smp + 20480 + (c&1)*16896, pv, tid);
        CP_WAIT0; __syncthreads();
        if (c < 31) {
            if (tid < 256)
                cpa_tile16<128>(aoff[(c+1)&1], Ap, NF, Ap, NF, 1<<30, (c+1)*32, tid);
            CP_COMMIT;
            ldgV512(pv, Vb, (c+1)*32, tid);
        }
        comp16_av2(aoff[c&1], sbase + 20480u + (unsigned)(c&1)*16896u, av, wr, wc2, lane);
    }
    float* P = g_avp + ((size_t)ks*B_ + b)*128*256;
    #pragma unroll
    for (int m2 = 0; m2 < 2; m2++)
        #pragma unroll
        for (int nt = 0; nt < 8; nt++) {
            int r = wr + m2*16 + g, c = wc2 + nt*8 + 2*t;
            *(float2*)&P[(size_t)r*256 + c]     = make_float2(av[m2][nt][0], av[m2][nt][1]);
            *(float2*)&P[(size_t)(r+8)*256 + c] = make_float2(av[m2][nt][2], av[m2][nt][3]);
        }
}

// ---------------- 7) combine split-K + rowinv + renorm ----------------
__global__ void av_combine_kernel()
{
    __shared__ float sinv[16];
    int idx = blockIdx.x * 256 + threadIdx.x;
    int row0 = (blockIdx.x * 256) >> 6;
    if (threadIdx.x < 16) {
        int row = row0 + threadIdx.x;
        int b = row >> 7, n = row & 127;
        float s = 0.f;
        #pragma unroll 8
        for (int mt = 0; mt < NMT; mt++) s += g_srow[(b*NMT + mt)*128 + n];
        sinv[threadIdx.x] = 1.f / (s + 1e-8f);
    }
    __syncthreads();
    int row = idx >> 6;
    float inv = sinv[row - row0];
    const size_t STR = (size_t)B_*NS*SD;
    float4 p0 = *(float4*)&g_avp[(size_t)idx*4];
    float4 p1 = *(float4*)&g_avp[STR   + (size_t)idx*4];
    float4 p2 = *(float4*)&g_avp[2*STR + (size_t)idx*4];
    float4 p3 = *(float4*)&g_avp[3*STR + (size_t)idx*4];
    float4 o;
    o.x = (p0.x + p1.x + p2.x + p3.x) * inv;
    o.y = (p0.y + p1.y + p2.y + p3.y) * inv;
    o.z = (p0.z + p1.z + p2.z + p3.z) * inv;
    o.w = (p0.w + p1.w + p2.w + p3.w) * inv;
    *(float4*)&g_fattn[(size_t)idx*4] = o;
    __half2 h0 = __floats2half2_rn(o.x, o.y), h1 = __floats2half2_rn(o.z, o.w);
    uint2 u = {*(unsigned*)&h0, *(unsigned*)&h1};
    *(uint2*)&g_fattn_h[(size_t)idx*4] = u;
}

// ---------------- 8) H = relu([snF|fattn] @ Wf0^T) ----------------
__global__ __launch_bounds__(256) void gemm_ff0_h()
{
    extern __shared__ unsigned char smp[];
    unsigned sbase = (unsigned)__cvta_generic_to_shared(smp);
    int tid = threadIdx.x, lane = tid & 31;
    int g = lane >> 2, t = lane & 3;
    int wid = tid >> 5, wr = (wid >> 1) * 32, wc = (wid & 1) * 64;
    int bm = blockIdx.x * 128, bn = blockIdx.y * 128;
    float acc[2][8][4] = {};
    h_gemm_async3<2, 128>(sbase, g_snF_h + (size_t)bm*256, 256, g_fattn_h + (size_t)bm*256, 256, 256,
                          g_Wf0_h + (size_t)bn*512, 512, 16, acc, wr, wc, lane, tid);
    #pragma unroll
    for (int mt = 0; mt < 2; mt++)
        #pragma unroll
        for (int nt = 0; nt < 8; nt++) {
            int r = bm + wr + mt*16 + g, c = bn + wc + nt*8 + 2*t;
            __half2 h0 = __floats2half2_rn(fmaxf(acc[mt][nt][0],0.f), fmaxf(acc[mt][nt][1],0.f));
            __half2 h1 = __floats2half2_rn(fmaxf(acc[mt][nt][2],0.f), fmaxf(acc[mt][nt][3],0.f));
            *(__half2*)&g_Hbuf_h[(size_t)r*1024 + c]     = h0;
            *(__half2*)&g_Hbuf_h[(size_t)(r+8)*1024 + c] = h1;
        }
}

// ---------------- 9) out = sigmoid([snA|fattn]@Wg^T)*fattn + H@Wf1^T (BM=64,BN=64) ----------------
__global__ __launch_bounds__(256) void gemm_out_h(float* __restrict__ out)
{
    extern __shared__ unsigned char smp[];
    unsigned sbase = (unsigned)__cvta_generic_to_shared(smp);
    int tid = threadIdx.x, lane = tid & 31;
    int g = lane >> 2, t = lane & 3;
    int wid = tid >> 5, wr = (wid >> 1) * 16, wc = (wid & 1) * 32;
    int bm = blockIdx.x * 64, bn = blockIdx.y * 64;
    float acc[1][4][4] = {};
    h_gemm_async3<1, 64>(sbase, g_snA_h + (size_t)bm*256, 256, g_fattn_h + (size_t)bm*256, 256, 256,
                         g_Wg_h + (size_t)bn*512, 512, 16, acc, wr, wc, lane, tid);
    #pragma unroll
    for (int nt = 0; nt < 4; nt++) {
        int r = bm + wr + g, c = bn + wc + nt*8 + 2*t;
        float2 f0 = *(const float2*)&g_fattn[(size_t)r*256 + c];
        float2 f1 = *(const float2*)&g_fattn[(size_t)(r+8)*256 + c];
        acc[0][nt][0] = f0.x / (1.f + __expf(-acc[0][nt][0]));
        acc[0][nt][1] = f0.y / (1.f + __expf(-acc[0][nt][1]));
        acc[0][nt][2] = f1.x / (1.f + __expf(-acc[0][nt][2]));
        acc[0][nt][3] = f1.y / (1.f + __expf(-acc[0][nt][3]));
    }
    h_gemm_async3<1, 64>(sbase, g_Hbuf_h + (size_t)bm*1024, 1024, g_Hbuf_h, 1024, 1<<30,
                         g_Wf1_h + (size_t)bn*1024, 1024, 32, acc, wr, wc, lane, tid);
    #pragma unroll
    for (int nt = 0; nt < 4; nt++) {
        int r = bm + wr + g, c = bn + wc + nt*8 + 2*t;
        *(float2*)&out[(size_t)r*256 + c]     = make_float2(acc[0][nt][0], acc[0][nt][1]);
        *(float2*)&out[(size_t)(r+8)*256 + c] = make_float2(acc[0][nt][2], acc[0][nt][3]);
    }
}

// ---------------- host launcher ----------------
extern "C" void kernel_launch(void* const* d_in, const int* in_sizes, int n_in,
                              void* d_out, int out_size)
{
    const float *t, *slots, *kin, *vin;
    const float *w0[4], *b0[4], *w1[4], *b1[4], *wp[4], *bp[4];
    const float *lnAw, *lnAb, *lnFw, *lnFb;

    if (in_sizes[0] == 1) {
        t     = (const float*)d_in[0];
        slots = (const float*)d_in[1];
        kin   = (const float*)d_in[2];
        vin   = (const float*)d_in[3];
        for (int h = 0; h < 4; h++) {
            int base = 4 + h*6;
            w0[h] = (const float*)d_in[base+0];  b0[h] = (const float*)d_in[base+1];
            w1[h] = (const float*)d_in[base+2];  b1[h] = (const float*)d_in[base+3];
            wp[h] = (const float*)d_in[base+4];  bp[h] = (const float*)d_in[base+5];
        }
        lnAw = (const float*)d_in[28]; lnAb = (const float*)d_in[29];
        lnFw = (const float*)d_in[30]; lnFb = (const float*)d_in[31];
    } else {
        for (int h = 0; h < 4; h++) {
            int base = h*6;
            w0[h] = (const float*)d_in[base+0];  b0[h] = (const float*)d_in[base+1];
            w1[h] = (const float*)d_in[base+2];  b1[h] = (const float*)d_in[base+3];
            wp[h] = (const float*)d_in[base+4];  bp[h] = (const float*)d_in[base+5];
        }
        lnAw = (const float*)d_in[24]; lnAb = (const float*)d_in[25];
        lnFw = (const float*)d_in[26]; lnFb = (const float*)d_in[27];
        t     = (const float*)d_in[28];
        slots = (const float*)d_in[29];
        kin   = (const float*)d_in[30];
        vin   = (const float*)d_in[31];
    }

    cudaStream_t s2;
    cudaEvent_t evF0, evT, evL, evJ;
    cudaStreamCreateWithFlags(&s2, cudaStreamNonBlocking);
    cudaEventCreateWithFlags(&evF0, cudaEventDisableTiming);
    cudaEventCreateWithFlags(&evT,  cudaEventDisableTiming);
    cudaEventCreateWithFlags(&evL,  cudaEventDisableTiming);
    cudaEventCreateWithFlags(&evJ,  cudaEventDisableTiming);

    // fork s2 from the capture origin FIRST (capture rule), then put ln on it
    cudaEventRecord(evF0, 0);
    cudaStreamWaitEvent(s2, evF0, 0);
    ln_kernel<<<(B_*NS)/8, 256, 0, s2>>>(slots, lnAw, lnAb, lnFw, lnFb);
    cudaEventRecord(evL, s2);

    tdw_kernel<<<4, 128>>>(t,
        w0[0],b0[0],w1[0],b1[0],  w0[1],b0[1],w1[1],b1[1],
        w0[2],b0[2],w1[2],b1[2],  w0[3],b0[3],w1[3],b1[3]);
    cudaEventRecord(evT, 0);
    cudaStreamWaitEvent(s2, evT, 0);
    wmat_rest_kernel<<<14336, 256, 0, s2>>>(wp[1],bp[1], wp[2],bp[2], wp[3],bp[3]);
    cudaEventRecord(evJ, s2);

    wmat_q_kernel<<<1024, 256>>>(wp[0], bp[0]);

    const int SMEM_Q   = 3*(64*80 + 64*80);     // 30720
    const int SMEM_FF0 = 3*(128*80 + 128*80);   // 61440
    const int SMEM_OUT = 3*(64*80 + 64*80);     // 30720
    const int SMEM_AV  = 20480 + 2*16896;       // 54272

    // gemm_q needs ln's snA
    cudaStreamWaitEvent(0, evL, 0);
    cudaFuncSetAttribute(gemm_q_h, cudaFuncAttributeMaxDynamicSharedMemorySize, SMEM_Q);
    gemm_q_h<<<dim3(64, 4), 256, SMEM_Q>>>();

    cudaFuncSetAttribute(attn_qk_kernel, cudaFuncAttributeMaxDynamicSharedMemorySize, QK_SMEM);
    attn_qk_kernel<<<1024, 256, QK_SMEM>>>(kin);

    cudaFuncSetAttribute(attn_av_kernel, cudaFuncAttributeMaxDynamicSharedMemorySize, SMEM_AV);
    attn_av_kernel<<<dim3(B_, 4), 512, SMEM_AV>>>(vin);

    av_combine_kernel<<<(B_*NS*SD/4)/256, 256>>>();

    // join: ff0/out need Wf0 / Wg / Wf1
    cudaStreamWaitEvent(0, evJ, 0);

    cudaFuncSetAttribute(gemm_ff0_h, cudaFuncAttributeMaxDynamicSharedMemorySize, SMEM_FF0);
    gemm_ff0_h<<<dim3(32, 8), 256, SMEM_FF0>>>();

    cudaFuncSetAttribute(gemm_out_h, cudaFuncAttributeMaxDynamicSharedMemorySize, SMEM_OUT);
    gemm_out_h<<<dim3(64, 4), 256, SMEM_OUT>>>((float*)d_out);
}

// round 16
// speedup vs baseline: 1.1946x; 1.1946x over previous
#include <cuda_runtime.h>
#include <cuda_fp16.h>

#define B_    32
#define NS    128
#define SD    256
#define NF    4096
#define MH    1024
#define NMT   32

// ---------------- device scratch ----------------
__device__ float g_h[4][64];
__device__ __align__(16) __half g_Wq_h [SD*SD];
__device__ __align__(16) __half g_Wg_h [SD*2*SD];
__device__ __align__(16) __half g_Wf0_h[MH*2*SD];
__device__ __align__(16) __half g_Wf1_h[SD*MH];
__device__ __align__(16) __half g_snA_h[B_*NS*SD];
__device__ __align__(16) __half g_snF_h[B_*NS*SD];
__device__ __align__(16) __half g_q_h  [B_*NS*SD];
__device__ __align__(16) __half g_att_h[(size_t)B_*NS*NF];   // 32 MB fp16 probs
__device__ __align__(16) __half g_fattn_h[B_*NS*SD];
__device__ __align__(16) __half g_Hbuf_h[B_*NS*MH];
__device__ float g_srow[B_*NMT*NS];
__device__ float g_avp[(size_t)4*B_*NS*SD];
__device__ __align__(16) float g_fattn[B_*NS*SD];

// ---------------- helpers ----------------
#define CP_COMMIT asm volatile("cp.async.commit_group;\n" ::: "memory")
#define CP_WAIT0  asm volatile("cp.async.wait_group 0;\n" ::: "memory")
#define CP_WAIT1  asm volatile("cp.async.wait_group 1;\n" ::: "memory")
__device__ __forceinline__ void cpa16(unsigned d, const void* s) {
    asm volatile("cp.async.ca.shared.global [%0], [%1], 16;\n" :: "r"(d), "l"(s));
}
__device__ __forceinline__ void mma16(float c[4], const unsigned a[4], const unsigned b[2]) {
    asm volatile("mma.sync.aligned.m16n8k16.row.col.f32.f16.f16.f32 "
        "{%0,%1,%2,%3},{%4,%5,%6,%7},{%8,%9},{%0,%1,%2,%3};"
        : "+f"(c[0]), "+f"(c[1]), "+f"(c[2]), "+f"(c[3])
        : "r"(a[0]), "r"(a[1]), "r"(a[2]), "r"(a[3]), "r"(b[0]), "r"(b[1]));
}
__device__ __forceinline__ void ldsm4(unsigned r[4], unsigned addr) {
    asm volatile("ldmatrix.sync.aligned.m8n8.x4.shared.b16 {%0,%1,%2,%3}, [%4];"
        : "=r"(r[0]), "=r"(r[1]), "=r"(r[2]), "=r"(r[3]) : "r"(addr));
}
__device__ __forceinline__ void ldsm4t(unsigned r[4], unsigned addr) {
    asm volatile("ldmatrix.sync.aligned.m8n8.x4.trans.shared.b16 {%0,%1,%2,%3}, [%4];"
        : "=r"(r[0]), "=r"(r[1]), "=r"(r[2]), "=r"(r[3]) : "r"(addr));
}
__device__ __forceinline__ uint4 pack8(const float4& a, const float4& b) {
    __half2 h0 = __floats2half2_rn(a.x, a.y), h1 = __floats2half2_rn(a.z, a.w);
    __half2 h2 = __floats2half2_rn(b.x, b.y), h3 = __floats2half2_rn(b.z, b.w);
    uint4 u;
    u.x = *(unsigned*)&h0; u.y = *(unsigned*)&h1;
    u.z = *(unsigned*)&h2; u.w = *(unsigned*)&h3;
    return u;
}

// ---- cp.async of a BM x 32-half tile, smem row stride 80 B ----
template<int BM>
__device__ __forceinline__ void cpa_tile16(unsigned sb, const __half* a0, int lda0,
                                           const __half* a1, int lda1, int split,
                                           int k0, int tid)
{
    if (BM == 128) {
        int r = tid >> 1, s = tid & 1;
        #pragma unroll
        for (int j = 0; j < 2; j++) {
            int k = k0 + s*16 + j*8;
            const __half* src = (k < split) ? a0 + (size_t)r*lda0 + k
                                            : a1 + (size_t)r*lda1 + (k - split);
            cpa16(sb + (unsigned)(r*80 + s*32 + j*16), src);
        }
    } else {   // BM == 64
        int r = tid >> 2, s = tid & 3;
        int k = k0 + s*8;
        const __half* src = (k < split) ? a0 + (size_t)r*lda0 + k
                                        : a1 + (size_t)r*lda1 + (k - split);
        cpa16(sb + (unsigned)(r*80 + s*16), src);
    }
}

// ---- mma.sync inner compute: BK=32 chunk, A/B in [rows][32k] 80B-stride ----
template<int MT, int NT16>
__device__ __forceinline__ void comp16(unsigned Ab, unsigned Bb,
                                       float acc[][NT16*2][4], int wr, int wc, int lane)
{
    int quad = lane >> 3, l7 = lane & 7;
    #pragma unroll
    for (int s = 0; s < 2; s++) {
        unsigned a[MT][4];
        #pragma unroll
        for (int mt = 0; mt < MT; mt++)
            ldsm4(a[mt], Ab + (unsigned)((wr + mt*16 + (quad&1)*8 + l7)*80 + s*32 + (quad>>1)*16));
        #pragma unroll
        for (int nt16 = 0; nt16 < NT16; nt16++) {
            unsigned bm4[4];
            ldsm4(bm4, Bb + (unsigned)((wc + nt16*16 + (quad>>1)*8 + l7)*80 + s*32 + (quad&1)*16));
            #pragma unroll
            for (int oct = 0; oct < 2; oct++)
                #pragma unroll
                for (int mt = 0; mt < MT; mt++)
                    mma16(acc[mt][nt16*2+oct], a[mt], &bm4[oct*2]);
        }
    }
}
// ---- AV inner compute (512-thr layout): warp owns 32 rows x 64 cols ----
__device__ __forceinline__ void comp16_av2(unsigned Ab, unsigned Bb,
                                           float av[2][8][4], int wr, int wc2, int lane)
{
    int quad = lane >> 3, l7 = lane & 7;
    #pragma unroll
    for (int s = 0; s < 2; s++) {
        unsigned a[2][4];
        #pragma unroll
        for (int m2 = 0; m2 < 2; m2++)
            ldsm4(a[m2], Ab + (unsigned)((wr + m2*16 + (quad&1)*8 + l7)*80 + s*32 + (quad>>1)*16));
        #pragma unroll
        for (int nt16 = 0; nt16 < 4; nt16++) {
            unsigned bm4[4];
            ldsm4t(bm4, Bb + (unsigned)((s*16 + (quad&1)*8 + l7)*528 + (wc2 + nt16*16 + (quad>>1)*8)*2));
            #pragma unroll
            for (int oct = 0; oct < 2; oct++)
                #pragma unroll
                for (int m2 = 0; m2 < 2; m2++)
                    mma16(av[m2][nt16*2+oct], a[m2], &bm4[oct*2]);
        }
    }
}

// ---- 3-stage cp.async pipelined fp16 GEMM; NB = B tile rows (64 or 128) ----
template<int MT, int NB>
__device__ __forceinline__ void h_gemm_async3(unsigned sbase,
    const __half* a0, int lda0, const __half* a1, int lda1, int split,
    const __half* b, int ldb, int nchunks,
    float acc[][NB/16][4], int wr, int wc, int lane, int tid)
{
    const unsigned ABUF = MT*64*80, BBUF = NB*80;
    unsigned st[3];
    #pragma unroll
    for (int s = 0; s < 3; s++) st[s] = sbase + (unsigned)s*(ABUF + BBUF);
    #pragma unroll
    for (int s = 0; s < 2; s++) {
        cpa_tile16<MT*64>(st[s], a0, lda0, a1, lda1, split, s*32, tid);
        cpa_tile16<NB>(st[s] + ABUF, b, ldb, b, ldb, 1<<30, s*32, tid);
        CP_COMMIT;
    }
    for (int c = 0; c < nchunks; c++) {
        CP_WAIT1;
        __syncthreads();
        int cn = c + 2;
        if (cn < nchunks) {
            unsigned ss = st[cn % 3];
            cpa_tile16<MT*64>(ss, a0, lda0, a1, lda1, split, cn*32, tid);
            cpa_tile16<NB>(ss + ABUF, b, ldb, b, ldb, 1<<30, cn*32, tid);
        }
        CP_COMMIT;
        unsigned sc = st[c % 3];
        comp16<MT, NB/32>(sc, sc + ABUF, acc, wr, wc, lane);
    }
    CP_WAIT0;
    __syncthreads();
}

// ---- staged fp32->fp16 loaders ----
__device__ __forceinline__ void ldgK(float4 p[4], const float* Kb, int k0, int tid) {
    int n = tid >> 1, c0 = (tid & 1) * 16;
    const float* s = Kb + (size_t)n*256 + k0 + c0;
    #pragma unroll
    for (int j = 0; j < 4; j++) p[j] = ((const float4*)s)[j];
}
__device__ __forceinline__ void stsK(unsigned char* buf, const float4 p[4], int tid) {
    int n = tid >> 1, c0 = tid & 1;
    *(uint4*)(buf + n*80 + c0*32)      = pack8(p[0], p[1]);
    *(uint4*)(buf + n*80 + c0*32 + 16) = pack8(p[2], p[3]);
}
__device__ __forceinline__ void ldgV512(float4 p[4], const float* Vb, int m0, int tid) {
    int k = tid >> 4, d0 = (tid & 15) * 16;
    const float* s = Vb + (size_t)(m0 + k)*256 + d0;
    #pragma unroll
    for (int j = 0; j < 4; j++) p[j] = ((const float4*)s)[j];
}
__device__ __forceinline__ void stsV512(unsigned char* buf, const float4 p[4], int tid) {
    int k = tid >> 4, d0 = (tid & 15) * 16;
    *(uint4*)(buf + k*528 + d0*2)      = pack8(p[0], p[1]);
    *(uint4*)(buf + k*528 + d0*2 + 16) = pack8(p[2], p[3]);
}

// ---- W-materialize row compute (8 warps x 8 rows per 256-thr CTA) ----
__device__ __forceinline__ void wmat_compute(const float* __restrict__ wp,
                                             const float* __restrict__ bp,
                                             const float* __restrict__ hv,
                                             __half* W, int r, int sub)
{
    float p = 0.f;
    #pragma unroll
    for (int j = 0; j < 4; j++) {
        float4 w  = *(const float4*)&wp[(size_t)r*64 + sub*16 + 4*j];
        float4 hh = *(const float4*)&hv[sub*16 + 4*j];
        p += w.x*hh.x + w.y*hh.y + w.z*hh.z + w.w*hh.w;
    }
    p += __shfl_down_sync(0xffffffffu, p, 2);
    p += __shfl_down_sync(0xffffffffu, p, 1);
    if (sub == 0) W[r] = __float2half_rn(p + bp[r]);
}

// ---------------- 1) time MLP heads ----------------
__global__ void tdw_kernel(const float* t,
    const float* qw0,const float* qb0,const float* qw1,const float* qb1,
    const float* gw0,const float* gb0,const float* gw1,const float* gb1,
    const float* f0w0,const float* f0b0,const float* f0w1,const float* f0b1,
    const float* f1w0,const float* f1b0,const float* f1w1,const float* f1b1)
{
    __shared__ float emb[257];
    __shared__ float h0[64];
    const float* w0s[4] = {qw0,gw0,f0w0,f1w0};
    const float* b0s[4] = {qb0,gb0,f0b0,f1b0};
    const float* w1s[4] = {qw1,gw1,f0w1,f1w1};
    const float* b1s[4] = {qb1,gb1,f0b1,f1b1};
    int head = blockIdx.x, tid = threadIdx.x;
    float tv = t[0];
    const float C = -9.210340371976184f / 128.0f;
    for (int j = tid; j < 257; j += blockDim.x) {
        float e;
        if (j == 0)        e = tv;
        else if (j <= 128) e = sinf(C * (float)(j-1)   * tv);
        else               e = cosf(C * (float)(j-129) * tv);
        emb[j] = e;
    }
    __syncthreads();
    int warp = tid >> 5, lane = tid & 31;
    const float* w0 = w0s[head];
    for (int r = warp; r < 64; r += 4) {
        float s = 0.f;
        for (int j = lane; j < 257; j += 32) s += w0[r*257 + j] * emb[j];
        #pragma unroll
        for (int o = 16; o; o >>= 1) s += __shfl_xor_sync(0xffffffffu, s, o);
        if (lane == 0) { s += b0s[head][r]; h0[r] = s / (1.f + expf(-s)); }
    }
    __syncthreads();
    if (tid < 64) {
        const float* w1 = w1s[head];
        float s = 0.f;
        #pragma unroll 8
        for (int j = 0; j < 64; j++) s += w1[tid*64 + j] * h0[j];
        s += b1s[head][tid];
        g_h[head][tid] = s / (1.f + expf(-s));
    }
}

// ---------------- 2a) materialize Wq (stream 0, needed by gemm_q) ----------------
__global__ void wmat_q_kernel(const float* __restrict__ wp, const float* __restrict__ bp)
{
    int wid = threadIdx.x >> 5, lane = threadIdx.x & 31;
    int rl = lane >> 2, sub = lane & 3;
    int r = (blockIdx.x * 8 + wid) * 8 + rl;     // < 65536
    wmat_compute(wp, bp, g_h[0], g_Wq_h, r, sub);
}

// ---------------- 2b) materialize Wg/Wf0/Wf1 (side stream) ----------------
__global__ void wmat_rest_kernel(const float* __restrict__ wp_g,  const float* __restrict__ bp_g,
                                 const float* __restrict__ wp_f0, const float* __restrict__ bp_f0,
                                 const float* __restrict__ wp_f1, const float* __restrict__ bp_f1)
{
    int wid = threadIdx.x >> 5, lane = threadIdx.x & 31;
    int rl = lane >> 2, sub = lane & 3;
    int r8 = 65536 + ((blockIdx.x * 8 + wid) * 8 + rl);
    const float* wp; const float* bp; __half* W; int r; int which;
    if (r8 < 196608)      { wp = wp_g;  bp = bp_g;  W = g_Wg_h;  r = r8 - 65536;  which = 1; }
    else if (r8 < 720896) { wp = wp_f0; bp = bp_f0; W = g_Wf0_h; r = r8 - 196608; which = 2; }
    else                  { wp = wp_f1; bp = bp_f1; W = g_Wf1_h; r = r8 - 720896; which = 3; }
    wmat_compute(wp, bp, g_h[which], W, r, sub);
}

// ---------------- 3) dual LayerNorm (fp16 out; side stream, no deps) ----------------
__global__ void ln_kernel(const float* __restrict__ slots,
                          const float* __restrict__ aw, const float* __restrict__ ab,
                          const float* __restrict__ fw, const float* __restrict__ fb)
{
    int warp = threadIdx.x >> 5, lane = threadIdx.x & 31;
    int row  = blockIdx.x * 8 + warp;
    const float* x = slots + (size_t)row * 256;
    float v[8];
    *(float4*)&v[0] = *(const float4*)&x[lane*4];
    *(float4*)&v[4] = *(const float4*)&x[128 + lane*4];
    float s = 0.f;
    #pragma unroll
    for (int i = 0; i < 8; i++) s += v[i];
    #pragma unroll
    for (int o = 16; o; o >>= 1) s += __shfl_xor_sync(0xffffffffu, s, o);
    float mu = s * (1.f/256.f);
    float q = 0.f;
    #pragma unroll
    for (int i = 0; i < 8; i++) { float d = v[i]-mu; q += d*d; }
    #pragma unroll
    for (int o = 16; o; o >>= 1) q += __shfl_xor_sync(0xffffffffu, q, o);
    float rstd = rsqrtf(q * (1.f/256.f) + 1e-5f);
    #pragma unroll
    for (int h = 0; h < 2; h++) {
        int base = h ? 128 + lane*4 : lane*4;
        float4 awv = *(const float4*)&aw[base], abv = *(const float4*)&ab[base];
        float4 fwv = *(const float4*)&fw[base], fbv = *(const float4*)&fb[base];
        const float* vv = &v[h*4];
        float A0=(vv[0]-mu)*rstd*awv.x+abv.x, A1=(vv[1]-mu)*rstd*awv.y+abv.y;
        float A2=(vv[2]-mu)*rstd*awv.z+abv.z, A3=(vv[3]-mu)*rstd*awv.w+abv.w;
        float F0=(vv[0]-mu)*rstd*fwv.x+fbv.x, F1=(vv[1]-mu)*rstd*fwv.y+fbv.y;
        float F2=(vv[2]-mu)*rstd*fwv.z+fbv.z, F3=(vv[3]-mu)*rstd*fwv.w+fbv.w;
        __half2 a01 = __floats2half2_rn(A0, A1), a23 = __floats2half2_rn(A2, A3);
        __half2 f01 = __floats2half2_rn(F0, F1), f23 = __floats2half2_rn(F2, F3);
        *(uint2*)&g_snA_h[(size_t)row*256 + base] = make_uint2(*(unsigned*)&a01, *(unsigned*)&a23);
        *(uint2*)&g_snF_h[(size_t)row*256 + base] = make_uint2(*(unsigned*)&f01, *(unsigned*)&f23);
    }
}

// ---------------- 4) q = snA @ Wq^T (BM=64, BN=64, grid 256) ----------------
__global__ __launch_bounds__(256) void gemm_q_h()
{
    extern __shared__ unsigned char smp[];
    unsigned sbase = (unsigned)__cvta_generic_to_shared(smp);
    int tid = threadIdx.x, lane = tid & 31;
    int g = lane >> 2, t = lane & 3;
    int wid = tid >> 5, wr = (wid >> 1) * 16, wc = (wid & 1) * 32;
    int bm = blockIdx.x * 64, bn = blockIdx.y * 64;
    float acc[1][4][4] = {};
    h_gemm_async3<1, 64>(sbase, g_snA_h + (size_t)bm*256, 256, g_snA_h, 256, 1<<30,
                         g_Wq_h + (size_t)bn*256, 256, 8, acc, wr, wc, lane, tid);
    #pragma unroll
    for (int nt = 0; nt < 4; nt++) {
        int r = bm + wr + g, c = bn + wc + nt*8 + 2*t;
        __half2 h0 = __floats2half2_rn(acc[0][nt][0], acc[0][nt][1]);
        __half2 h1 = __floats2half2_rn(acc[0][nt][2], acc[0][nt][3]);
        *(__half2*)&g_q_h[(size_t)r*256 + c]     = h0;
        *(__half2*)&g_q_h[(size_t)(r+8)*256 + c] = h1;
    }
}

// ---------------- 5) QK^T + softmax -> fp16 probs (2 CTAs/SM, proven config) ----------------
#define QK_RED  67584u
#define QK_SMEM 68608

__global__ __launch_bounds__(256, 2) void attn_qk_kernel(const float* __restrict__ Kin)
{
    extern __shared__ unsigned char smp[];
    unsigned sbase = (unsigned)__cvta_generic_to_shared(smp);
    float* L   = (float*)smp;
    float* RED = (float*)(smp + QK_RED);
    unsigned qoff[2] = {sbase, sbase + 10240u};
    unsigned koff[2] = {sbase + 20480u, sbase + 30720u};
    int bid = blockIdx.x;
    int b = bid >> 5, mt_ = bid & 31;
    int tid = threadIdx.x, lane = tid & 31;
    int g = lane >> 2, t = lane & 3;
    int wid = tid >> 5, wr = (wid >> 1) * 32, wc = (wid & 1) * 64;
    const __half* Q = g_q_h + (size_t)b*128*256;
    const float* Kb = Kin + ((size_t)b*NF + mt_*128)*256;
    float qk[2][8][4] = {};
    cpa_tile16<128>(qoff[0], Q, 256, Q, 256, 1<<30, 0, tid);
    CP_COMMIT;
    float4 pk[4];
    ldgK(pk, Kb, 0, tid);
    for (int c = 0; c < 8; c++) {
        stsK(smp + 20480 + (c&1)*10240, pk, tid);
        CP_WAIT0; __syncthreads();
        if (c < 7) {
            cpa_tile16<128>(qoff[(c+1)&1], Q, 256, Q, 256, 1<<30, (c+1)*32, tid);
            CP_COMMIT;
            ldgK(pk, Kb, (c+1)*32, tid);
        }
        comp16<2, 4>(qoff[c&1], koff[c&1], qk, wr, wc, lane);
    }
    __syncthreads();
    const float scale = 0.0625f;
    #pragma unroll
    for (int m2 = 0; m2 < 2; m2++)
        #pragma unroll
        for (int nt = 0; nt < 8; nt++) {
            int r = wr + m2*16 + g, c = wc + nt*8 + 2*t;
            L[r*132 + c]       = qk[m2][nt][0]*scale;
            L[r*132 + c+1]     = qk[m2][nt][1]*scale;
            L[(r+8)*132 + c]   = qk[m2][nt][2]*scale;
            L[(r+8)*132 + c+1] = qk[m2][nt][3]*scale;
        }
    __syncthreads();
    int half = tid >> 7, m = tid & 127, r0 = half * 64;
    float mx = -1e30f;
    #pragma unroll 8
    for (int r = 0; r < 64; r++) mx = fmaxf(mx, L[(r0+r)*132 + m]);
    RED[half*128 + m] = mx;
    __syncthreads();
    mx = fmaxf(RED[m], RED[128 + m]);
    float s = 0.f;
    #pragma unroll 8
    for (int r = 0; r < 64; r++) {
        float e = __expf(L[(r0+r)*132 + m] - mx);
        L[(r0+r)*132 + m] = e;
        s += e;
    }
    __syncthreads();
    RED[half*128 + m] = s;
    __syncthreads();
    float inv = 1.f / (RED[m] + RED[128 + m]);
    #pragma unroll 8
    for (int r = 0; r < 64; r++) L[(r0+r)*132 + m] *= inv;
    __syncthreads();
    {
        int n = m;
        float rs = 0.f;
        #pragma unroll 8
        for (int j = 0; j < 64; j++) rs += L[n*132 + half*64 + j];
        RED[half*128 + n] = rs;
    }
    __syncthreads();
    if (tid < 128)
        g_srow[((size_t)b*NMT + mt_)*128 + tid] = RED[tid] + RED[128 + tid];
    int n = tid >> 1, mh = (tid & 1) * 64;
    __half* dst = g_att_h + ((size_t)b*128 + n)*NF + mt_*128 + mh;
    #pragma unroll
    for (int j = 0; j < 8; j++) {
        float4 v0 = *(float4*)&L[n*132 + mh + 8*j];
        float4 v1 = *(float4*)&L[n*132 + mh + 8*j + 4];
        *(uint4*)(dst + 8*j) = pack8(v0, v1);
    }
}

// ---------------- 6) att @ V (split-K=4, 512 threads) ----------------
// smem: A probs dbl [0,20480), V dbl [20480, 20480+2*16896) = 54272 B
__global__ __launch_bounds__(512) void attn_av_kernel(const float* __restrict__ Vin)
{
    extern __shared__ unsigned char smp[];
    unsigned sbase = (unsigned)__cvta_generic_to_shared(smp);
    unsigned aoff[2] = {sbase, sbase + 10240u};
    int b = blockIdx.x, ks = blockIdx.y;
    int tid = threadIdx.x, lane = tid & 31;
    int g = lane >> 2, t = lane & 3;
    int wid = tid >> 5;
    int wr  = (wid >> 2) * 32;
    int wc2 = (wid & 3) * 64;
    const __half* Ap = g_att_h + (size_t)b*128*NF + ks*1024;
    const float* Vb = Vin + ((size_t)b*NF + ks*1024)*256;
    float av[2][8][4];
    #pragma unroll
    for (int i = 0; i < 2; i++)
        #pragma unroll
        for (int j = 0; j < 8; j++)
            #pragma unroll
            for (int k = 0; k < 4; k++) av[i][j][k] = 0.f;
    if (tid < 256) cpa_tile16<128>(aoff[0], Ap, NF, Ap, NF, 1<<30, 0, tid);
    CP_COMMIT;
    float4 pv[4];
    ldgV512(pv, Vb, 0, tid);
    for (int c = 0; c < 32; c++) {
        stsV512(smp + 20480 + (c&1)*16896, pv, tid);
        CP_WAIT0; __syncthreads();
        if (c < 31) {
            if (tid < 256)
                cpa_tile16<128>(aoff[(c+1)&1], Ap, NF, Ap, NF, 1<<30, (c+1)*32, tid);
            CP_COMMIT;
            ldgV512(pv, Vb, (c+1)*32, tid);
        }
        comp16_av2(aoff[c&1], sbase + 20480u + (unsigned)(c&1)*16896u, av, wr, wc2, lane);
    }
    float* P = g_avp + ((size_t)ks*B_ + b)*128*256;
    #pragma unroll
    for (int m2 = 0; m2 < 2; m2++)
        #pragma unroll
        for (int nt = 0; nt < 8; nt++) {
            int r = wr + m2*16 + g, c = wc2 + nt*8 + 2*t;
            *(float2*)&P[(size_t)r*256 + c]     = make_float2(av[m2][nt][0], av[m2][nt][1]);
            *(float2*)&P[(size_t)(r+8)*256 + c] = make_float2(av[m2][nt][2], av[m2][nt][3]);
        }
}

// ---------------- 7) combine split-K + rowinv + renorm ----------------
__global__ void av_combine_kernel()
{
    __shared__ float sinv[16];
    int idx = blockIdx.x * 256 + threadIdx.x;
    int row0 = (blockIdx.x * 256) >> 6;
    if (threadIdx.x < 16) {
        int row = row0 + threadIdx.x;
        int b = row >> 7, n = row & 127;
        float s = 0.f;
        #pragma unroll 8
        for (int mt = 0; mt < NMT; mt++) s += g_srow[(b*NMT + mt)*128 + n];
        sinv[threadIdx.x] = 1.f / (s + 1e-8f);
    }
    __syncthreads();
    int row = idx >> 6;
    float inv = sinv[row - row0];
    const size_t STR = (size_t)B_*NS*SD;
    float4 p0 = *(float4*)&g_avp[(size_t)idx*4];
    float4 p1 = *(float4*)&g_avp[STR   + (size_t)idx*4];
    float4 p2 = *(float4*)&g_avp[2*STR + (size_t)idx*4];
    float4 p3 = *(float4*)&g_avp[3*STR + (size_t)idx*4];
    float4 o;
    o.x = (p0.x + p1.x + p2.x + p3.x) * inv;
    o.y = (p0.y + p1.y + p2.y + p3.y) * inv;
    o.z = (p0.z + p1.z + p2.z + p3.z) * inv;
    o.w = (p0.w + p1.w + p2.w + p3.w) * inv;
    *(float4*)&g_fattn[(size_t)idx*4] = o;
    __half2 h0 = __floats2half2_rn(o.x, o.y), h1 = __floats2half2_rn(o.z, o.w);
    uint2 u = {*(unsigned*)&h0, *(unsigned*)&h1};
    *(uint2*)&g_fattn_h[(size_t)idx*4] = u;
}

// ---------------- 8) H = relu([snF|fattn] @ Wf0^T) ----------------
__global__ __launch_bounds__(256) void gemm_ff0_h()
{
    extern __shared__ unsigned char smp[];
    unsigned sbase = (unsigned)__cvta_generic_to_shared(smp);
    int tid = threadIdx.x, lane = tid & 31;
    int g = lane >> 2, t = lane & 3;
    int wid = tid >> 5, wr = (wid >> 1) * 32, wc = (wid & 1) * 64;
    int bm = blockIdx.x * 128, bn = blockIdx.y * 128;
    float acc[2][8][4] = {};
    h_gemm_async3<2, 128>(sbase, g_snF_h + (size_t)bm*256, 256, g_fattn_h + (size_t)bm*256, 256, 256,
                          g_Wf0_h + (size_t)bn*512, 512, 16, acc, wr, wc, lane, tid);
    #pragma unroll
    for (int mt = 0; mt < 2; mt++)
        #pragma unroll
        for (int nt = 0; nt < 8; nt++) {
            int r = bm + wr + mt*16 + g, c = bn + wc + nt*8 + 2*t;
            __half2 h0 = __floats2half2_rn(fmaxf(acc[mt][nt][0],0.f), fmaxf(acc[mt][nt][1],0.f));
            __half2 h1 = __floats2half2_rn(fmaxf(acc[mt][nt][2],0.f), fmaxf(acc[mt][nt][3],0.f));
            *(__half2*)&g_Hbuf_h[(size_t)r*1024 + c]     = h0;
            *(__half2*)&g_Hbuf_h[(size_t)(r+8)*1024 + c] = h1;
        }
}

// ---------------- 9) out = sigmoid([snA|fattn]@Wg^T)*fattn + H@Wf1^T (BM=64,BN=64) ----------------
__global__ __launch_bounds__(256) void gemm_out_h(float* __restrict__ out)
{
    extern __shared__ unsigned char smp[];
    unsigned sbase = (unsigned)__cvta_generic_to_shared(smp);
    int tid = threadIdx.x, lane = tid & 31;
    int g = lane >> 2, t = lane & 3;
    int wid = tid >> 5, wr = (wid >> 1) * 16, wc = (wid & 1) * 32;
    int bm = blockIdx.x * 64, bn = blockIdx.y * 64;
    float acc[1][4][4] = {};
    h_gemm_async3<1, 64>(sbase, g_snA_h + (size_t)bm*256, 256, g_fattn_h + (size_t)bm*256, 256, 256,
                         g_Wg_h + (size_t)bn*512, 512, 16, acc, wr, wc, lane, tid);
    #pragma unroll
    for (int nt = 0; nt < 4; nt++) {
        int r = bm + wr + g, c = bn + wc + nt*8 + 2*t;
        float2 f0 = *(const float2*)&g_fattn[(size_t)r*256 + c];
        float2 f1 = *(const float2*)&g_fattn[(size_t)(r+8)*256 + c];
        acc[0][nt][0] = f0.x / (1.f + __expf(-acc[0][nt][0]));
        acc[0][nt][1] = f0.y / (1.f + __expf(-acc[0][nt][1]));
        acc[0][nt][2] = f1.x / (1.f + __expf(-acc[0][nt][2]));
        acc[0][nt][3] = f1.y / (1.f + __expf(-acc[0][nt][3]));
    }
    h_gemm_async3<1, 64>(sbase, g_Hbuf_h + (size_t)bm*1024, 1024, g_Hbuf_h, 1024, 1<<30,
                         g_Wf1_h + (size_t)bn*1024, 1024, 32, acc, wr, wc, lane, tid);
    #pragma unroll
    for (int nt = 0; nt < 4; nt++) {
        int r = bm + wr + g, c = bn + wc + nt*8 + 2*t;
        *(float2*)&out[(size_t)r*256 + c]     = make_float2(acc[0][nt][0], acc[0][nt][1]);
        *(float2*)&out[(size_t)(r+8)*256 + c] = make_float2(acc[0][nt][2], acc[0][nt][3]);
    }
}

// ---------------- host launcher ----------------
extern "C" void kernel_launch(void* const* d_in, const int* in_sizes, int n_in,
                              void* d_out, int out_size)
{
    const float *t, *slots, *kin, *vin;
    const float *w0[4], *b0[4], *w1[4], *b1[4], *wp[4], *bp[4];
    const float *lnAw, *lnAb, *lnFw, *lnFb;

    if (in_sizes[0] == 1) {
        t     = (const float*)d_in[0];
        slots = (const float*)d_in[1];
        kin   = (const float*)d_in[2];
        vin   = (const float*)d_in[3];
        for (int h = 0; h < 4; h++) {
            int base = 4 + h*6;
            w0[h] = (const float*)d_in[base+0];  b0[h] = (const float*)d_in[base+1];
            w1[h] = (const float*)d_in[base+2];  b1[h] = (const float*)d_in[base+3];
            wp[h] = (const float*)d_in[base+4];  bp[h] = (const float*)d_in[base+5];
        }
        lnAw = (const float*)d_in[28]; lnAb = (const float*)d_in[29];
        lnFw = (const float*)d_in[30]; lnFb = (const float*)d_in[31];
    } else {
        for (int h = 0; h < 4; h++) {
            int base = h*6;
            w0[h] = (const float*)d_in[base+0];  b0[h] = (const float*)d_in[base+1];
            w1[h] = (const float*)d_in[base+2];  b1[h] = (const float*)d_in[base+3];
            wp[h] = (const float*)d_in[base+4];  bp[h] = (const float*)d_in[base+5];
        }
        lnAw = (const float*)d_in[24]; lnAb = (const float*)d_in[25];
        lnFw = (const float*)d_in[26]; lnFb = (const float*)d_in[27];
        t     = (const float*)d_in[28];
        slots = (const float*)d_in[29];
        kin   = (const float*)d_in[30];
        vin   = (const float*)d_in[31];
    }

    cudaStream_t s2;
    cudaEvent_t evF0, evT, evL, evJ;
    cudaStreamCreateWithFlags(&s2, cudaStreamNonBlocking);
    cudaEventCreateWithFlags(&evF0, cudaEventDisableTiming);
    cudaEventCreateWithFlags(&evT,  cudaEventDisableTiming);
    cudaEventCreateWithFlags(&evL,  cudaEventDisableTiming);
    cudaEventCreateWithFlags(&evJ,  cudaEventDisableTiming);

    // fork s2 from the capture origin FIRST (capture rule), then put ln on it
    cudaEventRecord(evF0, 0);
    cudaStreamWaitEvent(s2, evF0, 0);
    ln_kernel<<<(B_*NS)/8, 256, 0, s2>>>(slots, lnAw, lnAb, lnFw, lnFb);
    cudaEventRecord(evL, s2);

    tdw_kernel<<<4, 128>>>(t,
        w0[0],b0[0],w1[0],b1[0],  w0[1],b0[1],w1[1],b1[1],
        w0[2],b0[2],w1[2],b1[2],  w0[3],b0[3],w1[3],b1[3]);
    cudaEventRecord(evT, 0);
    cudaStreamWaitEvent(s2, evT, 0);
    wmat_rest_kernel<<<14336, 256, 0, s2>>>(wp[1],bp[1], wp[2],bp[2], wp[3],bp[3]);
    cudaEventRecord(evJ, s2);

    wmat_q_kernel<<<1024, 256>>>(wp[0], bp[0]);

    const int SMEM_Q   = 3*(64*80 + 64*80);     // 30720
    const int SMEM_FF0 = 3*(128*80 + 128*80);   // 61440
    const int SMEM_OUT = 3*(64*80 + 64*80);     // 30720
    const int SMEM_AV  = 20480 + 2*16896;       // 54272

    // gemm_q needs ln's snA
    cudaStreamWaitEvent(0, evL, 0);
    cudaFuncSetAttribute(gemm_q_h, cudaFuncAttributeMaxDynamicSharedMemorySize, SMEM_Q);
    gemm_q_h<<<dim3(64, 4), 256, SMEM_Q>>>();

    cudaFuncSetAttribute(attn_qk_kernel, cudaFuncAttributeMaxDynamicSharedMemorySize, QK_SMEM);
    attn_qk_kernel<<<1024, 256, QK_SMEM>>>(kin);

    cudaFuncSetAttribute(attn_av_kernel, cudaFuncAttributeMaxDynamicSharedMemorySize, SMEM_AV);
    attn_av_kernel<<<dim3(B_, 4), 512, SMEM_AV>>>(vin);

    av_combine_kernel<<<(B_*NS*SD/4)/256, 256>>>();

    // join: ff0/out need Wf0 / Wg / Wf1
    cudaStreamWaitEvent(0, evJ, 0);

    cudaFuncSetAttribute(gemm_ff0_h, cudaFuncAttributeMaxDynamicSharedMemorySize, SMEM_FF0);
    gemm_ff0_h<<<dim3(32, 8), 256, SMEM_FF0>>>();

    cudaFuncSetAttribute(gemm_out_h, cudaFuncAttributeMaxDynamicSharedMemorySize, SMEM_OUT);
    gemm_out_h<<<dim3(64, 4), 256, SMEM_OUT>>>((float*)d_out);
}